// round 7
// baseline (speedup 1.0000x reference)
#include <cuda_runtime.h>
#include <math.h>

#define N_NODES   100000
#define N_EDGES   1600000
#define N_GRAPHS  64
#define IN_FEATS  64
#define HIDDEN    32
#define OUT_DIM   2
#define CHUNKS    512
#define SCAN_B    1024
#define NCHUNK    ((N_NODES + SCAN_B - 1) / SCAN_B)   // 98

// Scratch (device globals — no allocation allowed)
__device__ __align__(16) float g_x32 [N_NODES * HIDDEN];   // x1 then x2 (reused)
__device__ __align__(16) float g_agg1[N_NODES * HIDDEN];
__device__ __align__(16) float g_agg2[N_NODES * HIDDEN];
__device__ __align__(16) float g_x3  [N_NODES * OUT_DIM];
__device__ __align__(16) float g_gsum[N_GRAPHS * IN_FEATS];
__device__ float g_gcnt[N_GRAPHS];
__device__ float g_c2  [HIDDEN];             // b1 @ W2
__device__ float g_c3  [OUT_DIM];            // b2 @ W3
// CSR-by-destination
__device__ int   g_cnt   [N_NODES];
__device__ int   g_rowptr[N_NODES + 1];
__device__ int   g_cursor[N_NODES];
__device__ int   g_esrc  [N_EDGES];
__device__ int   g_bsum  [NCHUNK];

__global__ void k_fill0v(float4* __restrict__ p, int n4) {
    int i = blockIdx.x * blockDim.x + threadIdx.x;
    if (i < n4) p[i] = make_float4(0.f, 0.f, 0.f, 0.f);
}
__global__ void k_fill0i(int* __restrict__ p, int n) {
    int i = blockIdx.x * blockDim.x + threadIdx.x;
    if (i < n) p[i] = 0;
}

// ---- CSR construction ----
__global__ void k_hist(const int* __restrict__ dst, int* __restrict__ cnt) {
    int e = blockIdx.x * blockDim.x + threadIdx.x;
    if (e < N_EDGES) atomicAdd(&cnt[__ldg(dst + e)], 1);
}

// per-chunk exclusive scan (1024 threads), chunk total -> bsum
__global__ void k_scan1(const int* __restrict__ cnt, int* __restrict__ rowptr,
                        int* __restrict__ bsum) {
    __shared__ int s[SCAN_B];
    int t = threadIdx.x;
    int i = blockIdx.x * SCAN_B + t;
    int v = (i < N_NODES) ? cnt[i] : 0;
    s[t] = v;
    __syncthreads();
    #pragma unroll
    for (int off = 1; off < SCAN_B; off <<= 1) {
        int add = (t >= off) ? s[t - off] : 0;
        __syncthreads();
        s[t] += add;
        __syncthreads();
    }
    if (i < N_NODES) rowptr[i] = s[t] - v;       // exclusive
    if (t == SCAN_B - 1) bsum[blockIdx.x] = s[t];
}

// scan chunk totals (tiny: NCHUNK=98, single thread)
__global__ void k_scan2(int* __restrict__ bsum) {
    if (threadIdx.x != 0) return;
    int run = 0;
    for (int b = 0; b < NCHUNK; b++) { int t = bsum[b]; bsum[b] = run; run += t; }
}

// add chunk offsets; init cursor; close rowptr
__global__ void k_scan3(int* __restrict__ rowptr, const int* __restrict__ bsum,
                        int* __restrict__ cursor) {
    int i = blockIdx.x * blockDim.x + threadIdx.x;
    if (i < N_NODES) {
        int r = rowptr[i] + bsum[i >> 10];
        rowptr[i] = r;
        cursor[i] = r;
    }
    if (i == 0) rowptr[N_NODES] = N_EDGES;
}

__global__ void k_reorder(const int* __restrict__ src, const int* __restrict__ dst,
                          int* __restrict__ cursor, int* __restrict__ esrc) {
    int e = blockIdx.x * blockDim.x + threadIdx.x;
    if (e >= N_EDGES) return;
    int d = __ldg(dst + e);
    int pos = atomicAdd(&cursor[d], 1);
    esrc[pos] = __ldg(src + e);
}

// ---- dense GEMVs ----
__global__ void k_bias(const float* __restrict__ b1, const float* __restrict__ W2,
                       const float* __restrict__ b2, const float* __restrict__ W3,
                       float* __restrict__ c2, float* __restrict__ c3) {
    int j = threadIdx.x;
    if (j < HIDDEN) {
        float s = 0.f;
        for (int k = 0; k < HIDDEN; k++) s += b1[k] * W2[k * HIDDEN + j];
        c2[j] = s;
    }
    if (j < OUT_DIM) {
        float s = 0.f;
        for (int k = 0; k < HIDDEN; k++) s += b2[k] * W3[k * OUT_DIM + j];
        c3[j] = s;
    }
}

__global__ void k_mm1(const float* __restrict__ nf, const float* __restrict__ W1,
                      float* __restrict__ x) {
    __shared__ float Ws[IN_FEATS * HIDDEN];
    for (int i = threadIdx.x; i < IN_FEATS * HIDDEN; i += blockDim.x) Ws[i] = W1[i];
    __syncthreads();
    int warp   = (blockIdx.x * blockDim.x + threadIdx.x) >> 5;
    int lane   = threadIdx.x & 31;
    int nwarps = (gridDim.x * blockDim.x) >> 5;
    for (int n = warp; n < N_NODES; n += nwarps) {
        const float* row = nf + (size_t)n * IN_FEATS;
        float r0 = row[lane], r1 = row[lane + 32];
        float acc = 0.f;
        #pragma unroll
        for (int k = 0; k < 32; k++)
            acc += __shfl_sync(0xffffffffu, r0, k) * Ws[k * HIDDEN + lane];
        #pragma unroll
        for (int k = 0; k < 32; k++)
            acc += __shfl_sync(0xffffffffu, r1, k) * Ws[(k + 32) * HIDDEN + lane];
        x[(size_t)n * HIDDEN + lane] = acc;
    }
}

__global__ void k_mm2(const float* __restrict__ agg, const float* __restrict__ W2,
                      const float* __restrict__ c2, float* __restrict__ x) {
    __shared__ float Ws[HIDDEN * HIDDEN];
    for (int i = threadIdx.x; i < HIDDEN * HIDDEN; i += blockDim.x) Ws[i] = W2[i];
    __syncthreads();
    int warp   = (blockIdx.x * blockDim.x + threadIdx.x) >> 5;
    int lane   = threadIdx.x & 31;
    int nwarps = (gridDim.x * blockDim.x) >> 5;
    float bias = c2[lane];
    for (int n = warp; n < N_NODES; n += nwarps) {
        float r = agg[(size_t)n * HIDDEN + lane];
        float acc = bias;
        #pragma unroll
        for (int k = 0; k < 32; k++)
            acc += __shfl_sync(0xffffffffu, r, k) * Ws[k * HIDDEN + lane];
        x[(size_t)n * HIDDEN + lane] = acc;
    }
}

__global__ void k_mm3(const float* __restrict__ agg2, const float* __restrict__ W3,
                      const float* __restrict__ c3, float* __restrict__ x3) {
    __shared__ float Ws[HIDDEN * OUT_DIM];
    if (threadIdx.x < HIDDEN * OUT_DIM) Ws[threadIdx.x] = W3[threadIdx.x];
    __syncthreads();
    int n = blockIdx.x * blockDim.x + threadIdx.x;
    if (n >= N_NODES) return;
    float a0 = c3[0], a1 = c3[1];
    const float4* row = (const float4*)(agg2 + (size_t)n * HIDDEN);
    #pragma unroll
    for (int q = 0; q < 8; q++) {
        float4 v = row[q];
        int k = q * 4;
        a0 += v.x * Ws[(k + 0) * 2 + 0]; a1 += v.x * Ws[(k + 0) * 2 + 1];
        a0 += v.y * Ws[(k + 1) * 2 + 0]; a1 += v.y * Ws[(k + 1) * 2 + 1];
        a0 += v.z * Ws[(k + 2) * 2 + 0]; a1 += v.z * Ws[(k + 2) * 2 + 1];
        a0 += v.w * Ws[(k + 3) * 2 + 0]; a1 += v.w * Ws[(k + 3) * 2 + 1];
    }
    x3[(size_t)n * 2 + 0] = a0;
    x3[(size_t)n * 2 + 1] = a1;
}

// ---- CSR gathers (no atomics) ----
// agg[n][lane] = sum_{e in in(n)} x[esrc[e]][lane] ; warp per node, lane = feature
__global__ void k_gather32(const float* __restrict__ x, float* __restrict__ agg,
                           const int* __restrict__ rowptr, const int* __restrict__ esrc) {
    int warp = (blockIdx.x * blockDim.x + threadIdx.x) >> 5;
    int lane = threadIdx.x & 31;
    if (warp >= N_NODES) return;
    int e  = __ldg(rowptr + warp);
    int e1 = __ldg(rowptr + warp + 1);
    float acc = 0.f;
    // 4-way unroll for MLP across the index->gather dependency
    for (; e + 4 <= e1; e += 4) {
        int s0 = __ldg(esrc + e + 0);
        int s1 = __ldg(esrc + e + 1);
        int s2 = __ldg(esrc + e + 2);
        int s3 = __ldg(esrc + e + 3);
        float v0 = __ldg(x + (size_t)s0 * HIDDEN + lane);
        float v1 = __ldg(x + (size_t)s1 * HIDDEN + lane);
        float v2 = __ldg(x + (size_t)s2 * HIDDEN + lane);
        float v3 = __ldg(x + (size_t)s3 * HIDDEN + lane);
        acc += (v0 + v1) + (v2 + v3);
    }
    for (; e < e1; e++)
        acc += __ldg(x + (size_t)__ldg(esrc + e) * HIDDEN + lane);
    agg[(size_t)warp * HIDDEN + lane] = acc;
}

// h3[n][j] = sum_e x3[esrc[e]][j] + b3[j] ; warp per node, lanes parallel over edges
__global__ void k_gather2(const float* __restrict__ x3, float* __restrict__ h3,
                          const int* __restrict__ rowptr, const int* __restrict__ esrc,
                          const float* __restrict__ b3) {
    int warp = (blockIdx.x * blockDim.x + threadIdx.x) >> 5;
    int lane = threadIdx.x & 31;
    if (warp >= N_NODES) return;
    int e0 = __ldg(rowptr + warp);
    int e1 = __ldg(rowptr + warp + 1);
    float a0 = 0.f, a1 = 0.f;
    for (int e = e0 + lane; e < e1; e += 32) {
        int s = __ldg(esrc + e);
        float2 v = *(const float2*)(x3 + (size_t)s * 2);
        a0 += v.x; a1 += v.y;
    }
    #pragma unroll
    for (int off = 16; off > 0; off >>= 1) {
        a0 += __shfl_xor_sync(0xffffffffu, a0, off);
        a1 += __shfl_xor_sync(0xffffffffu, a1, off);
    }
    if (lane == 0) {
        h3[(size_t)warp * 2 + 0] = a0 + __ldg(b3 + 0);
        h3[(size_t)warp * 2 + 1] = a1 + __ldg(b3 + 1);
    }
}

// ---- graph head ----
__global__ void k_gsum(const float* __restrict__ nf, const int* __restrict__ gid,
                       float* __restrict__ gsum, float* __restrict__ gcnt) {
    int t = blockIdx.x * blockDim.x + threadIdx.x;
    if (t >= CHUNKS * IN_FEATS) return;
    int f = t & (IN_FEATS - 1);
    int chunk = t >> 6;
    const int per = (N_NODES + CHUNKS - 1) / CHUNKS;
    int n0 = chunk * per;
    int n1 = n0 + per; if (n1 > N_NODES) n1 = N_NODES;
    if (n0 >= n1) return;
    float acc = 0.f;
    int curg = gid[n0];
    for (int n = n0; n < n1; n++) {
        int g = gid[n];
        if (g != curg) { atomicAdd(&gsum[curg * IN_FEATS + f], acc); acc = 0.f; curg = g; }
        acc += nf[(size_t)n * IN_FEATS + f];
    }
    atomicAdd(&gsum[curg * IN_FEATS + f], acc);
    if (f == 0) {
        float c = 0.f;
        int cg = gid[n0];
        for (int n = n0; n < n1; n++) {
            int g = gid[n];
            if (g != cg) { atomicAdd(&gcnt[cg], c); c = 0.f; cg = g; }
            c += 1.f;
        }
        atomicAdd(&gcnt[cg], c);
    }
}

__global__ void k_pred(const float* __restrict__ Wl, const float* __restrict__ bl,
                       const float* __restrict__ gsum, const float* __restrict__ gcnt,
                       float* __restrict__ out) {
    int g = threadIdx.x;
    if (g >= N_GRAPHS) return;
    float cnt = gcnt[g]; if (cnt < 1.f) cnt = 1.f;
    float s = bl[0];
    #pragma unroll 8
    for (int f = 0; f < IN_FEATS; f++)
        s += (gsum[g * IN_FEATS + f] / cnt) * Wl[f];
    out[g] = 1.f / (1.f + expf(-s));
}

extern "C" void kernel_launch(void* const* d_in, const int* in_sizes, int n_in,
                              void* d_out, int out_size) {
    const float* nf  = (const float*)d_in[0];
    // d_in[1] = edge_feats (unused by the reference model)
    const float* W1  = (const float*)d_in[2];
    const float* b1  = (const float*)d_in[3];
    const float* W2  = (const float*)d_in[4];
    const float* b2  = (const float*)d_in[5];
    const float* W3  = (const float*)d_in[6];
    const float* b3  = (const float*)d_in[7];
    const float* Wl  = (const float*)d_in[8];
    const float* bl  = (const float*)d_in[9];
    const int*   src = (const int*)d_in[10];
    const int*   dst = (const int*)d_in[11];
    const int*   gid = (const int*)d_in[12];
    float* out = (float*)d_out;

    float *p_x32, *p_agg1, *p_agg2, *p_x3, *p_gsum, *p_gcnt, *p_c2, *p_c3;
    int *p_cnt, *p_rowptr, *p_cursor, *p_esrc, *p_bsum;
    cudaGetSymbolAddress((void**)&p_x32,    g_x32);
    cudaGetSymbolAddress((void**)&p_agg1,   g_agg1);
    cudaGetSymbolAddress((void**)&p_agg2,   g_agg2);
    cudaGetSymbolAddress((void**)&p_x3,     g_x3);
    cudaGetSymbolAddress((void**)&p_gsum,   g_gsum);
    cudaGetSymbolAddress((void**)&p_gcnt,   g_gcnt);
    cudaGetSymbolAddress((void**)&p_c2,     g_c2);
    cudaGetSymbolAddress((void**)&p_c3,     g_c3);
    cudaGetSymbolAddress((void**)&p_cnt,    g_cnt);
    cudaGetSymbolAddress((void**)&p_rowptr, g_rowptr);
    cudaGetSymbolAddress((void**)&p_cursor, g_cursor);
    cudaGetSymbolAddress((void**)&p_esrc,   g_esrc);
    cudaGetSymbolAddress((void**)&p_bsum,   g_bsum);

    const int T = 256;

    // ---- CSR build (by destination) ----
    k_fill0i<<<(N_NODES + T - 1) / T, T>>>(p_cnt, N_NODES);
    k_hist<<<(N_EDGES + T - 1) / T, T>>>(dst, p_cnt);
    k_scan1<<<NCHUNK, SCAN_B>>>(p_cnt, p_rowptr, p_bsum);
    k_scan2<<<1, 32>>>(p_bsum);
    k_scan3<<<(N_NODES + T - 1) / T, T>>>(p_rowptr, p_bsum, p_cursor);
    k_reorder<<<(N_EDGES + T - 1) / T, T>>>(src, dst, p_cursor, p_esrc);

    // small head inits + folded biases (overlap with CSR build on same stream order)
    k_fill0v<<<(N_GRAPHS * IN_FEATS / 4 + T - 1) / T, T>>>((float4*)p_gsum, N_GRAPHS * IN_FEATS / 4);
    k_fill0v<<<1, N_GRAPHS / 4>>>((float4*)p_gcnt, N_GRAPHS / 4);
    k_bias<<<1, 32>>>(b1, W2, b2, W3, p_c2, p_c3);

    // layer 1: x1 = nf @ W1 ; agg1 = A x1 (gather)
    k_mm1<<<(N_NODES * 32 + T - 1) / T, T>>>(nf, W1, p_x32);
    k_gather32<<<(N_NODES * 32 + T - 1) / T, T>>>(p_x32, p_agg1, p_rowptr, p_esrc);
    // layer 2: x2 = agg1 @ W2 + b1@W2 ; agg2 = A x2 (gather)
    k_mm2<<<(N_NODES * 32 + T - 1) / T, T>>>(p_agg1, W2, p_c2, p_x32);
    k_gather32<<<(N_NODES * 32 + T - 1) / T, T>>>(p_x32, p_agg2, p_rowptr, p_esrc);
    // layer 3: x3 = agg2 @ W3 + b2@W3 ; h3 = A x3 + b3 (gather straight into out)
    k_mm3<<<(N_NODES + T - 1) / T, T>>>(p_agg2, W3, p_c3, p_x3);
    k_gather2<<<(N_NODES * 32 + T - 1) / T, T>>>(p_x3, out + N_GRAPHS, p_rowptr, p_esrc, b3);

    // graph head: mean-pool of original features -> sigmoid(linear)
    k_gsum<<<(CHUNKS * IN_FEATS + T - 1) / T, T>>>(nf, gid, p_gsum, p_gcnt);
    k_pred<<<1, N_GRAPHS>>>(Wl, bl, p_gsum, p_gcnt, out);
}

// round 9
// speedup vs baseline: 2.4044x; 2.4044x over previous
#include <cuda_runtime.h>
#include <math.h>

#define N_NODES   100000
#define N_EDGES   1600000
#define N_GRAPHS  64
#define IN_FEATS  64
#define HIDDEN    32
#define OUT_DIM   2
#define CHUNKS    512
#define E4        (N_EDGES / 4)

// Scratch (device globals — no allocation allowed)
__device__ __align__(16) float g_y4 [N_NODES * 4];   // (y0, y1, indeg, 0)
__device__ __align__(16) float g_z1 [N_NODES * 4];   // (A y)0,1 , s1, 0
__device__ __align__(16) float g_z2 [N_NODES * 2];   // A^2 y
__device__ __align__(16) float g_gsum[N_GRAPHS * IN_FEATS];
__device__ float g_gcnt[N_GRAPHS];
__device__ int   g_cnt [N_NODES];                    // indeg
__device__ __align__(16) float g_W123[IN_FEATS * OUT_DIM];  // W1@W2@W3  [64,2]
__device__ float g_cA[OUT_DIM];                      // b1@W2@W3
__device__ float g_cB[OUT_DIM];                      // b2@W3

__global__ void k_fill0v(float4* __restrict__ p, int n4) {
    int i = blockIdx.x * blockDim.x + threadIdx.x;
    if (i < n4) p[i] = make_float4(0.f, 0.f, 0.f, 0.f);
}
__global__ void k_fill0i(int* __restrict__ p, int n) {
    int i = blockIdx.x * blockDim.x + threadIdx.x;
    if (i < n) p[i] = 0;
}

// indeg histogram over dst
__global__ void k_hist(const int* __restrict__ dst, int* __restrict__ cnt) {
    int t = blockIdx.x * blockDim.x + threadIdx.x;
    if (t >= E4) return;
    int4 d = ((const int4*)dst)[t];
    atomicAdd(&cnt[d.x], 1);
    atomicAdd(&cnt[d.y], 1);
    atomicAdd(&cnt[d.z], 1);
    atomicAdd(&cnt[d.w], 1);
}

// Fold weights: W23 = W2@W3 [32,2]; W123 = W1@W23 [64,2]; cA = b1@W23; cB = b2@W3
__global__ void k_wfold(const float* __restrict__ W1, const float* __restrict__ b1,
                        const float* __restrict__ W2, const float* __restrict__ b2,
                        const float* __restrict__ W3,
                        float* __restrict__ W123, float* __restrict__ cA,
                        float* __restrict__ cB) {
    __shared__ float W23[HIDDEN * OUT_DIM];
    int t = threadIdx.x;
    if (t < HIDDEN * OUT_DIM) {
        int i = t >> 1, j = t & 1;
        float s = 0.f;
        for (int k = 0; k < HIDDEN; k++) s += W2[i * HIDDEN + k] * W3[k * OUT_DIM + j];
        W23[t] = s;
    }
    __syncthreads();
    if (t < IN_FEATS * OUT_DIM) {
        int i = t >> 1, j = t & 1;
        float s = 0.f;
        for (int k = 0; k < HIDDEN; k++) s += W1[i * HIDDEN + k] * W23[k * OUT_DIM + j];
        W123[t] = s;
    }
    if (t < OUT_DIM) {
        float sa = 0.f, sb = 0.f;
        for (int k = 0; k < HIDDEN; k++) {
            sa += b1[k] * W23[k * OUT_DIM + t];
            sb += b2[k] * W3[k * OUT_DIM + t];
        }
        cA[t] = sa;
        cB[t] = sb;
    }
}

// y4[n] = (nf[n]@W123, indeg[n], 0) ; thread per node
__global__ void k_y4(const float* __restrict__ nf, const float* __restrict__ W123,
                     const int* __restrict__ cnt, float4* __restrict__ y4) {
    __shared__ float Ws[IN_FEATS * OUT_DIM];
    if (threadIdx.x < IN_FEATS * OUT_DIM) Ws[threadIdx.x] = W123[threadIdx.x];
    __syncthreads();
    int n = blockIdx.x * blockDim.x + threadIdx.x;
    if (n >= N_NODES) return;
    const float4* row = (const float4*)(nf + (size_t)n * IN_FEATS);
    float a0 = 0.f, a1 = 0.f;
    #pragma unroll
    for (int q = 0; q < 16; q++) {
        float4 v = row[q];
        int k = q * 4;
        a0 += v.x * Ws[(k + 0) * 2 + 0]; a1 += v.x * Ws[(k + 0) * 2 + 1];
        a0 += v.y * Ws[(k + 1) * 2 + 0]; a1 += v.y * Ws[(k + 1) * 2 + 1];
        a0 += v.z * Ws[(k + 2) * 2 + 0]; a1 += v.z * Ws[(k + 2) * 2 + 1];
        a0 += v.w * Ws[(k + 3) * 2 + 0]; a1 += v.w * Ws[(k + 3) * 2 + 1];
    }
    y4[n] = make_float4(a0, a1, (float)__ldg(cnt + n), 0.f);
}

// pass1: Z1[dst] += y4[src]  (RED.128/edge, 4 edges per thread)
__global__ void k_pass1(const float* __restrict__ y4, float* __restrict__ z1,
                        const int* __restrict__ src, const int* __restrict__ dst) {
    int t = blockIdx.x * blockDim.x + threadIdx.x;
    if (t >= E4) return;
    int4 s = ((const int4*)src)[t];
    int4 d = ((const int4*)dst)[t];
    float4 v0 = *(const float4*)(y4 + (size_t)s.x * 4);
    float4 v1 = *(const float4*)(y4 + (size_t)s.y * 4);
    float4 v2 = *(const float4*)(y4 + (size_t)s.z * 4);
    float4 v3 = *(const float4*)(y4 + (size_t)s.w * 4);
    asm volatile("red.global.add.v4.f32 [%0], {%1, %2, %3, %4};"
                 :: "l"(z1 + (size_t)d.x * 4), "f"(v0.x), "f"(v0.y), "f"(v0.z), "f"(v0.w) : "memory");
    asm volatile("red.global.add.v4.f32 [%0], {%1, %2, %3, %4};"
                 :: "l"(z1 + (size_t)d.y * 4), "f"(v1.x), "f"(v1.y), "f"(v1.z), "f"(v1.w) : "memory");
    asm volatile("red.global.add.v4.f32 [%0], {%1, %2, %3, %4};"
                 :: "l"(z1 + (size_t)d.z * 4), "f"(v2.x), "f"(v2.y), "f"(v2.z), "f"(v2.w) : "memory");
    asm volatile("red.global.add.v4.f32 [%0], {%1, %2, %3, %4};"
                 :: "l"(z1 + (size_t)d.w * 4), "f"(v3.x), "f"(v3.y), "f"(v3.z), "f"(v3.w) : "memory");
}

// pass2: Z2[dst] += Z1[src].xy  (RED.64/edge, 4 edges per thread)
__global__ void k_pass2(const float* __restrict__ z1, float* __restrict__ z2,
                        const int* __restrict__ src, const int* __restrict__ dst) {
    int t = blockIdx.x * blockDim.x + threadIdx.x;
    if (t >= E4) return;
    int4 s = ((const int4*)src)[t];
    int4 d = ((const int4*)dst)[t];
    float2 v0 = *(const float2*)(z1 + (size_t)s.x * 4);
    float2 v1 = *(const float2*)(z1 + (size_t)s.y * 4);
    float2 v2 = *(const float2*)(z1 + (size_t)s.z * 4);
    float2 v3 = *(const float2*)(z1 + (size_t)s.w * 4);
    asm volatile("red.global.add.v2.f32 [%0], {%1, %2};"
                 :: "l"(z2 + (size_t)d.x * 2), "f"(v0.x), "f"(v0.y) : "memory");
    asm volatile("red.global.add.v2.f32 [%0], {%1, %2};"
                 :: "l"(z2 + (size_t)d.y * 2), "f"(v1.x), "f"(v1.y) : "memory");
    asm volatile("red.global.add.v2.f32 [%0], {%1, %2};"
                 :: "l"(z2 + (size_t)d.z * 2), "f"(v2.x), "f"(v2.y) : "memory");
    asm volatile("red.global.add.v2.f32 [%0], {%1, %2};"
                 :: "l"(z2 + (size_t)d.w * 2), "f"(v3.x), "f"(v3.y) : "memory");
}

// Seed h3: out[64+2n+j] = b3[j] + s1[n]*cA[j] + indeg[n]*cB[j]
__global__ void k_seed(float* __restrict__ out, const float* __restrict__ b3,
                       const float* __restrict__ z1, const int* __restrict__ cnt,
                       const float* __restrict__ cA, const float* __restrict__ cB) {
    int n = blockIdx.x * blockDim.x + threadIdx.x;
    if (n >= N_NODES) return;
    float s1   = z1[(size_t)n * 4 + 2];
    float degf = (float)__ldg(cnt + n);
    float o0 = __ldg(b3 + 0) + s1 * __ldg(cA + 0) + degf * __ldg(cB + 0);
    float o1 = __ldg(b3 + 1) + s1 * __ldg(cA + 1) + degf * __ldg(cB + 1);
    *(float2*)(out + N_GRAPHS + (size_t)n * 2) = make_float2(o0, o1);
}

// pass3: out[64+2*dst] += Z2[src]  (RED.64/edge)
__global__ void k_pass3(const float* __restrict__ z2, float* __restrict__ h3,
                        const int* __restrict__ src, const int* __restrict__ dst) {
    int t = blockIdx.x * blockDim.x + threadIdx.x;
    if (t >= E4) return;
    int4 s = ((const int4*)src)[t];
    int4 d = ((const int4*)dst)[t];
    float2 v0 = *(const float2*)(z2 + (size_t)s.x * 2);
    float2 v1 = *(const float2*)(z2 + (size_t)s.y * 2);
    float2 v2 = *(const float2*)(z2 + (size_t)s.z * 2);
    float2 v3 = *(const float2*)(z2 + (size_t)s.w * 2);
    asm volatile("red.global.add.v2.f32 [%0], {%1, %2};"
                 :: "l"(h3 + (size_t)d.x * 2), "f"(v0.x), "f"(v0.y) : "memory");
    asm volatile("red.global.add.v2.f32 [%0], {%1, %2};"
                 :: "l"(h3 + (size_t)d.y * 2), "f"(v1.x), "f"(v1.y) : "memory");
    asm volatile("red.global.add.v2.f32 [%0], {%1, %2};"
                 :: "l"(h3 + (size_t)d.z * 2), "f"(v2.x), "f"(v2.y) : "memory");
    asm volatile("red.global.add.v2.f32 [%0], {%1, %2};"
                 :: "l"(h3 + (size_t)d.w * 2), "f"(v3.x), "f"(v3.y) : "memory");
}

// ---- graph head (unchanged) ----
__global__ void k_gsum(const float* __restrict__ nf, const int* __restrict__ gid,
                       float* __restrict__ gsum, float* __restrict__ gcnt) {
    int t = blockIdx.x * blockDim.x + threadIdx.x;
    if (t >= CHUNKS * IN_FEATS) return;
    int f = t & (IN_FEATS - 1);
    int chunk = t >> 6;
    const int per = (N_NODES + CHUNKS - 1) / CHUNKS;
    int n0 = chunk * per;
    int n1 = n0 + per; if (n1 > N_NODES) n1 = N_NODES;
    if (n0 >= n1) return;
    float acc = 0.f;
    int curg = gid[n0];
    for (int n = n0; n < n1; n++) {
        int g = gid[n];
        if (g != curg) { atomicAdd(&gsum[curg * IN_FEATS + f], acc); acc = 0.f; curg = g; }
        acc += nf[(size_t)n * IN_FEATS + f];
    }
    atomicAdd(&gsum[curg * IN_FEATS + f], acc);
    if (f == 0) {
        float c = 0.f;
        int cg = gid[n0];
        for (int n = n0; n < n1; n++) {
            int g = gid[n];
            if (g != cg) { atomicAdd(&gcnt[cg], c); c = 0.f; cg = g; }
            c += 1.f;
        }
        atomicAdd(&gcnt[cg], c);
    }
}

__global__ void k_pred(const float* __restrict__ Wl, const float* __restrict__ bl,
                       const float* __restrict__ gsum, const float* __restrict__ gcnt,
                       float* __restrict__ out) {
    int g = threadIdx.x;
    if (g >= N_GRAPHS) return;
    float cnt = gcnt[g]; if (cnt < 1.f) cnt = 1.f;
    float s = bl[0];
    #pragma unroll 8
    for (int f = 0; f < IN_FEATS; f++)
        s += (gsum[g * IN_FEATS + f] / cnt) * Wl[f];
    out[g] = 1.f / (1.f + expf(-s));
}

extern "C" void kernel_launch(void* const* d_in, const int* in_sizes, int n_in,
                              void* d_out, int out_size) {
    const float* nf  = (const float*)d_in[0];
    // d_in[1] = edge_feats (unused by the reference model)
    const float* W1  = (const float*)d_in[2];
    const float* b1  = (const float*)d_in[3];
    const float* W2  = (const float*)d_in[4];
    const float* b2  = (const float*)d_in[5];
    const float* W3  = (const float*)d_in[6];
    const float* b3  = (const float*)d_in[7];
    const float* Wl  = (const float*)d_in[8];
    const float* bl  = (const float*)d_in[9];
    const int*   src = (const int*)d_in[10];
    const int*   dst = (const int*)d_in[11];
    const int*   gid = (const int*)d_in[12];
    float* out = (float*)d_out;

    float *p_y4, *p_z1, *p_z2, *p_gsum, *p_gcnt, *p_W123, *p_cA, *p_cB;
    int *p_cnt;
    cudaGetSymbolAddress((void**)&p_y4,   g_y4);
    cudaGetSymbolAddress((void**)&p_z1,   g_z1);
    cudaGetSymbolAddress((void**)&p_z2,   g_z2);
    cudaGetSymbolAddress((void**)&p_gsum, g_gsum);
    cudaGetSymbolAddress((void**)&p_gcnt, g_gcnt);
    cudaGetSymbolAddress((void**)&p_W123, g_W123);
    cudaGetSymbolAddress((void**)&p_cA,   g_cA);
    cudaGetSymbolAddress((void**)&p_cB,   g_cB);
    cudaGetSymbolAddress((void**)&p_cnt,  g_cnt);

    const int T = 256;

    // zero fills (small: ~2.5 MB total)
    k_fill0i<<<(N_NODES + T - 1) / T, T>>>(p_cnt, N_NODES);
    k_fill0v<<<(N_NODES + T - 1) / T, T>>>((float4*)p_z1, N_NODES);
    k_fill0v<<<(N_NODES / 2 + T - 1) / T, T>>>((float4*)p_z2, N_NODES / 2);
    k_fill0v<<<(N_GRAPHS * IN_FEATS / 4 + T - 1) / T, T>>>((float4*)p_gsum, N_GRAPHS * IN_FEATS / 4);
    k_fill0v<<<1, N_GRAPHS / 4>>>((float4*)p_gcnt, N_GRAPHS / 4);

    // indeg + folded weights
    k_hist<<<(E4 + T - 1) / T, T>>>(dst, p_cnt);
    k_wfold<<<1, 128>>>(W1, b1, W2, b2, W3, p_W123, p_cA, p_cB);

    // y4 = (nf@W123, indeg, 0)
    k_y4<<<(N_NODES + T - 1) / T, T>>>(nf, p_W123, p_cnt, (float4*)p_y4);

    // three aggregation passes
    k_pass1<<<(E4 + T - 1) / T, T>>>(p_y4, p_z1, src, dst);
    k_pass2<<<(E4 + T - 1) / T, T>>>(p_z1, p_z2, src, dst);
    k_seed <<<(N_NODES + T - 1) / T, T>>>(out, b3, p_z1, p_cnt, p_cA, p_cB);
    k_pass3<<<(E4 + T - 1) / T, T>>>(p_z2, out + N_GRAPHS, src, dst);

    // graph head: mean-pool of original features -> sigmoid(linear)
    k_gsum<<<(CHUNKS * IN_FEATS + T - 1) / T, T>>>(nf, gid, p_gsum, p_gcnt);
    k_pred<<<1, N_GRAPHS>>>(Wl, bl, p_gsum, p_gcnt, out);
}

// round 10
// speedup vs baseline: 2.7361x; 1.1380x over previous
#include <cuda_runtime.h>
#include <math.h>

#define N_NODES   100000
#define N_EDGES   1600000
#define N_GRAPHS  64
#define IN_FEATS  64
#define HIDDEN    32
#define OUT_DIM   2
#define CHUNKS    512
#define E4        (N_EDGES / 4)

// Scratch (device globals — no allocation allowed)
__device__ __align__(16) float g_y4[N_NODES * 4];    // (y0, y1, 1, 0)
__device__ __align__(16) float g_z [N_NODES * 8];    // z1 = [0:4N), z2 = [4N:8N)
                                                     // z1=(Ay, indeg, 0) z2=(A2y, s1, 0)
__device__ __align__(16) float g_gsum[N_GRAPHS * IN_FEATS];
__device__ __align__(16) float g_gcnt[N_GRAPHS];
__device__ __align__(16) float g_W123[IN_FEATS * OUT_DIM];  // W1@W2@W3  [64,2]
__device__ float g_cA[OUT_DIM];                      // b1@W2@W3
__device__ float g_cB[OUT_DIM];                      // b2@W3

#define NZ4  (N_NODES * 2)                 // g_z in float4s
#define GS4  (N_GRAPHS * IN_FEATS / 4)
#define GC4  (N_GRAPHS / 4)

// One launch zeroes everything
__global__ void k_fills(float4* __restrict__ z, float4* __restrict__ gsum,
                        float4* __restrict__ gcnt) {
    int i = blockIdx.x * blockDim.x + threadIdx.x;
    const float4 zero = make_float4(0.f, 0.f, 0.f, 0.f);
    if (i < NZ4)                 { z[i] = zero; return; }
    i -= NZ4;
    if (i < GS4)                 { gsum[i] = zero; return; }
    i -= GS4;
    if (i < GC4)                 { gcnt[i] = zero; }
}

// Fold weights: W23 = W2@W3 [32,2]; W123 = W1@W23 [64,2]; cA = b1@W23; cB = b2@W3
__global__ void k_wfold(const float* __restrict__ W1, const float* __restrict__ b1,
                        const float* __restrict__ W2, const float* __restrict__ b2,
                        const float* __restrict__ W3,
                        float* __restrict__ W123, float* __restrict__ cA,
                        float* __restrict__ cB) {
    __shared__ float W23[HIDDEN * OUT_DIM];
    int t = threadIdx.x;
    if (t < HIDDEN * OUT_DIM) {
        int i = t >> 1, j = t & 1;
        float s = 0.f;
        for (int k = 0; k < HIDDEN; k++) s += W2[i * HIDDEN + k] * W3[k * OUT_DIM + j];
        W23[t] = s;
    }
    __syncthreads();
    if (t < IN_FEATS * OUT_DIM) {
        int i = t >> 1, j = t & 1;
        float s = 0.f;
        for (int k = 0; k < HIDDEN; k++) s += W1[i * HIDDEN + k] * W23[k * OUT_DIM + j];
        W123[t] = s;
    }
    if (t < OUT_DIM) {
        float sa = 0.f, sb = 0.f;
        for (int k = 0; k < HIDDEN; k++) {
            sa += b1[k] * W23[k * OUT_DIM + t];
            sb += b2[k] * W3[k * OUT_DIM + t];
        }
        cA[t] = sa;
        cB[t] = sb;
    }
}

// y4[n] = (nf[n]@W123, 1, 0) ; thread per node
__global__ void k_y4(const float* __restrict__ nf, const float* __restrict__ W123,
                     float4* __restrict__ y4) {
    __shared__ float Ws[IN_FEATS * OUT_DIM];
    if (threadIdx.x < IN_FEATS * OUT_DIM) Ws[threadIdx.x] = W123[threadIdx.x];
    __syncthreads();
    int n = blockIdx.x * blockDim.x + threadIdx.x;
    if (n >= N_NODES) return;
    const float4* row = (const float4*)(nf + (size_t)n * IN_FEATS);
    float a0 = 0.f, a1 = 0.f;
    #pragma unroll
    for (int q = 0; q < 16; q++) {
        float4 v = row[q];
        int k = q * 4;
        a0 += v.x * Ws[(k + 0) * 2 + 0]; a1 += v.x * Ws[(k + 0) * 2 + 1];
        a0 += v.y * Ws[(k + 1) * 2 + 0]; a1 += v.y * Ws[(k + 1) * 2 + 1];
        a0 += v.z * Ws[(k + 2) * 2 + 0]; a1 += v.z * Ws[(k + 2) * 2 + 1];
        a0 += v.w * Ws[(k + 3) * 2 + 0]; a1 += v.w * Ws[(k + 3) * 2 + 1];
    }
    y4[n] = make_float4(a0, a1, 1.0f, 0.f);
}

// vout[dst] += vin[src]  (float4 rows, RED.128/edge, 4 edges per thread)
// Used for pass1 (y4->z1: .z accumulates indeg) and pass2 (z1->z2: .z accumulates s1)
__global__ void k_passv4(const float* __restrict__ vin, float* __restrict__ vout,
                         const int* __restrict__ src, const int* __restrict__ dst) {
    int t = blockIdx.x * blockDim.x + threadIdx.x;
    if (t >= E4) return;
    int4 s = ((const int4*)src)[t];
    int4 d = ((const int4*)dst)[t];
    float4 v0 = *(const float4*)(vin + (size_t)s.x * 4);
    float4 v1 = *(const float4*)(vin + (size_t)s.y * 4);
    float4 v2 = *(const float4*)(vin + (size_t)s.z * 4);
    float4 v3 = *(const float4*)(vin + (size_t)s.w * 4);
    asm volatile("red.global.add.v4.f32 [%0], {%1, %2, %3, %4};"
                 :: "l"(vout + (size_t)d.x * 4), "f"(v0.x), "f"(v0.y), "f"(v0.z), "f"(v0.w) : "memory");
    asm volatile("red.global.add.v4.f32 [%0], {%1, %2, %3, %4};"
                 :: "l"(vout + (size_t)d.y * 4), "f"(v1.x), "f"(v1.y), "f"(v1.z), "f"(v1.w) : "memory");
    asm volatile("red.global.add.v4.f32 [%0], {%1, %2, %3, %4};"
                 :: "l"(vout + (size_t)d.z * 4), "f"(v2.x), "f"(v2.y), "f"(v2.z), "f"(v2.w) : "memory");
    asm volatile("red.global.add.v4.f32 [%0], {%1, %2, %3, %4};"
                 :: "l"(vout + (size_t)d.w * 4), "f"(v3.x), "f"(v3.y), "f"(v3.z), "f"(v3.w) : "memory");
}

// Seed h3: out[64+2n+j] = b3[j] + s1[n]*cA[j] + indeg[n]*cB[j]
//   indeg[n] = z1[n].z ; s1[n] = z2[n].z
__global__ void k_seed(float* __restrict__ out, const float* __restrict__ b3,
                       const float* __restrict__ z1, const float* __restrict__ z2,
                       const float* __restrict__ cA, const float* __restrict__ cB) {
    int n = blockIdx.x * blockDim.x + threadIdx.x;
    if (n >= N_NODES) return;
    float degf = z1[(size_t)n * 4 + 2];
    float s1   = z2[(size_t)n * 4 + 2];
    float o0 = __ldg(b3 + 0) + s1 * __ldg(cA + 0) + degf * __ldg(cB + 0);
    float o1 = __ldg(b3 + 1) + s1 * __ldg(cA + 1) + degf * __ldg(cB + 1);
    *(float2*)(out + N_GRAPHS + (size_t)n * 2) = make_float2(o0, o1);
}

// pass3: out[64+2*dst] += z2[src].xy  (RED.64/edge, 4 edges per thread)
__global__ void k_pass3(const float* __restrict__ z2, float* __restrict__ h3,
                        const int* __restrict__ src, const int* __restrict__ dst) {
    int t = blockIdx.x * blockDim.x + threadIdx.x;
    if (t >= E4) return;
    int4 s = ((const int4*)src)[t];
    int4 d = ((const int4*)dst)[t];
    float2 v0 = *(const float2*)(z2 + (size_t)s.x * 4);
    float2 v1 = *(const float2*)(z2 + (size_t)s.y * 4);
    float2 v2 = *(const float2*)(z2 + (size_t)s.z * 4);
    float2 v3 = *(const float2*)(z2 + (size_t)s.w * 4);
    asm volatile("red.global.add.v2.f32 [%0], {%1, %2};"
                 :: "l"(h3 + (size_t)d.x * 2), "f"(v0.x), "f"(v0.y) : "memory");
    asm volatile("red.global.add.v2.f32 [%0], {%1, %2};"
                 :: "l"(h3 + (size_t)d.y * 2), "f"(v1.x), "f"(v1.y) : "memory");
    asm volatile("red.global.add.v2.f32 [%0], {%1, %2};"
                 :: "l"(h3 + (size_t)d.z * 2), "f"(v2.x), "f"(v2.y) : "memory");
    asm volatile("red.global.add.v2.f32 [%0], {%1, %2};"
                 :: "l"(h3 + (size_t)d.w * 2), "f"(v3.x), "f"(v3.y) : "memory");
}

// ---- graph head ----
__global__ void k_gsum(const float* __restrict__ nf, const int* __restrict__ gid,
                       float* __restrict__ gsum, float* __restrict__ gcnt) {
    int t = blockIdx.x * blockDim.x + threadIdx.x;
    if (t >= CHUNKS * IN_FEATS) return;
    int f = t & (IN_FEATS - 1);
    int chunk = t >> 6;
    const int per = (N_NODES + CHUNKS - 1) / CHUNKS;
    int n0 = chunk * per;
    int n1 = n0 + per; if (n1 > N_NODES) n1 = N_NODES;
    if (n0 >= n1) return;
    float acc = 0.f;
    int curg = gid[n0];
    for (int n = n0; n < n1; n++) {
        int g = gid[n];
        if (g != curg) { atomicAdd(&gsum[curg * IN_FEATS + f], acc); acc = 0.f; curg = g; }
        acc += nf[(size_t)n * IN_FEATS + f];
    }
    atomicAdd(&gsum[curg * IN_FEATS + f], acc);
    if (f == 0) {
        float c = 0.f;
        int cg = gid[n0];
        for (int n = n0; n < n1; n++) {
            int g = gid[n];
            if (g != cg) { atomicAdd(&gcnt[cg], c); c = 0.f; cg = g; }
            c += 1.f;
        }
        atomicAdd(&gcnt[cg], c);
    }
}

__global__ void k_pred(const float* __restrict__ Wl, const float* __restrict__ bl,
                       const float* __restrict__ gsum, const float* __restrict__ gcnt,
                       float* __restrict__ out) {
    int g = threadIdx.x;
    if (g >= N_GRAPHS) return;
    float cnt = gcnt[g]; if (cnt < 1.f) cnt = 1.f;
    float s = bl[0];
    #pragma unroll 8
    for (int f = 0; f < IN_FEATS; f++)
        s += (gsum[g * IN_FEATS + f] / cnt) * Wl[f];
    out[g] = 1.f / (1.f + expf(-s));
}

extern "C" void kernel_launch(void* const* d_in, const int* in_sizes, int n_in,
                              void* d_out, int out_size) {
    const float* nf  = (const float*)d_in[0];
    // d_in[1] = edge_feats (unused by the reference model)
    const float* W1  = (const float*)d_in[2];
    const float* b1  = (const float*)d_in[3];
    const float* W2  = (const float*)d_in[4];
    const float* b2  = (const float*)d_in[5];
    const float* W3  = (const float*)d_in[6];
    const float* b3  = (const float*)d_in[7];
    const float* Wl  = (const float*)d_in[8];
    const float* bl  = (const float*)d_in[9];
    const int*   src = (const int*)d_in[10];
    const int*   dst = (const int*)d_in[11];
    const int*   gid = (const int*)d_in[12];
    float* out = (float*)d_out;

    float *p_y4, *p_z, *p_gsum, *p_gcnt, *p_W123, *p_cA, *p_cB;
    cudaGetSymbolAddress((void**)&p_y4,   g_y4);
    cudaGetSymbolAddress((void**)&p_z,    g_z);
    cudaGetSymbolAddress((void**)&p_gsum, g_gsum);
    cudaGetSymbolAddress((void**)&p_gcnt, g_gcnt);
    cudaGetSymbolAddress((void**)&p_W123, g_W123);
    cudaGetSymbolAddress((void**)&p_cA,   g_cA);
    cudaGetSymbolAddress((void**)&p_cB,   g_cB);
    float* p_z1 = p_z;
    float* p_z2 = p_z + (size_t)N_NODES * 4;

    const int T = 256;

    // one fill pass for all accumulators
    k_fills<<<(NZ4 + GS4 + GC4 + T - 1) / T, T>>>((float4*)p_z, (float4*)p_gsum,
                                                  (float4*)p_gcnt);
    // folded weights
    k_wfold<<<1, 128>>>(W1, b1, W2, b2, W3, p_W123, p_cA, p_cB);

    // y4 = (nf@W123, 1, 0)
    k_y4<<<(N_NODES + T - 1) / T, T>>>(nf, p_W123, (float4*)p_y4);

    // aggregation passes (indeg and s1 ride in .z)
    k_passv4<<<(E4 + T - 1) / T, T>>>(p_y4, p_z1, src, dst);   // z1 = (Ay, indeg, 0)
    k_passv4<<<(E4 + T - 1) / T, T>>>(p_z1, p_z2, src, dst);   // z2 = (A2y, s1, 0)
    k_seed  <<<(N_NODES + T - 1) / T, T>>>(out, b3, p_z1, p_z2, p_cA, p_cB);
    k_pass3 <<<(E4 + T - 1) / T, T>>>(p_z2, out + N_GRAPHS, src, dst);

    // graph head: mean-pool of original features -> sigmoid(linear)
    k_gsum<<<(CHUNKS * IN_FEATS + T - 1) / T, T>>>(nf, gid, p_gsum, p_gcnt);
    k_pred<<<1, N_GRAPHS>>>(Wl, bl, p_gsum, p_gcnt, out);
}

// round 11
// speedup vs baseline: 2.7940x; 1.0212x over previous
#include <cuda_runtime.h>
#include <math.h>

#define N_NODES   100000
#define N_EDGES   1600000
#define N_GRAPHS  64
#define IN_FEATS  64
#define HIDDEN    32
#define OUT_DIM   2
#define CHUNKS    512
#define E4        (N_EDGES / 4)

// Scratch (device globals — no allocation allowed)
__device__ __align__(16) float g_y2 [N_NODES * 2];   // y = nf @ W123   (float2 rows)
__device__ __align__(16) float g_z  [N_NODES * 4];   // z1 = [0:2N), z2 = [2N:4N)
__device__ __align__(16) float g_gsum[N_GRAPHS * IN_FEATS];
__device__ __align__(16) float g_gcnt[N_GRAPHS];
__device__ __align__(16) float g_W123[IN_FEATS * OUT_DIM];  // W1@W2@W3  [64,2]
__device__ __align__(8) float g_cA[OUT_DIM];         // b1@W2@W3
__device__ __align__(8) float g_cB[OUT_DIM];         // b2@W3
__device__ __align__(8) float g_c0[OUT_DIM] = {0.f, 0.f};

#define NZ4  (N_NODES)                    // g_z in float4s (4N floats)
#define GS4  (N_GRAPHS * IN_FEATS / 4)
#define GC4  (N_GRAPHS / 4)
#define NO4  (N_NODES / 2)                // out h3 region in float4s (2N floats)

// One launch: zero z/gsum/gcnt AND seed out h3 region with b3 pattern
__global__ void k_fills(float4* __restrict__ z, float4* __restrict__ gsum,
                        float4* __restrict__ gcnt, float4* __restrict__ h3,
                        const float* __restrict__ b3) {
    int i = blockIdx.x * blockDim.x + threadIdx.x;
    const float4 zero = make_float4(0.f, 0.f, 0.f, 0.f);
    if (i < NZ4) { z[i] = zero; return; }
    i -= NZ4;
    if (i < GS4) { gsum[i] = zero; return; }
    i -= GS4;
    if (i < GC4) { gcnt[i] = zero; return; }
    i -= GC4;
    if (i < NO4) {
        float b0 = __ldg(b3 + 0), b1 = __ldg(b3 + 1);
        h3[i] = make_float4(b0, b1, b0, b1);
    }
}

// Fold weights: W23 = W2@W3 [32,2]; W123 = W1@W23 [64,2]; cA = b1@W23; cB = b2@W3
__global__ void k_wfold(const float* __restrict__ W1, const float* __restrict__ b1,
                        const float* __restrict__ W2, const float* __restrict__ b2,
                        const float* __restrict__ W3,
                        float* __restrict__ W123, float* __restrict__ cA,
                        float* __restrict__ cB) {
    __shared__ float W23[HIDDEN * OUT_DIM];
    int t = threadIdx.x;
    if (t < HIDDEN * OUT_DIM) {
        int i = t >> 1, j = t & 1;
        float s = 0.f;
        for (int k = 0; k < HIDDEN; k++) s += W2[i * HIDDEN + k] * W3[k * OUT_DIM + j];
        W23[t] = s;
    }
    __syncthreads();
    if (t < IN_FEATS * OUT_DIM) {
        int i = t >> 1, j = t & 1;
        float s = 0.f;
        for (int k = 0; k < HIDDEN; k++) s += W1[i * HIDDEN + k] * W23[k * OUT_DIM + j];
        W123[t] = s;
    }
    if (t < OUT_DIM) {
        float sa = 0.f, sb = 0.f;
        for (int k = 0; k < HIDDEN; k++) {
            sa += b1[k] * W23[k * OUT_DIM + t];
            sb += b2[k] * W3[k * OUT_DIM + t];
        }
        cA[t] = sa;
        cB[t] = sb;
    }
}

// y2[n] = nf[n] @ W123 ; thread per node
__global__ void k_y2(const float* __restrict__ nf, const float* __restrict__ W123,
                     float2* __restrict__ y2) {
    __shared__ float Ws[IN_FEATS * OUT_DIM];
    if (threadIdx.x < IN_FEATS * OUT_DIM) Ws[threadIdx.x] = W123[threadIdx.x];
    __syncthreads();
    int n = blockIdx.x * blockDim.x + threadIdx.x;
    if (n >= N_NODES) return;
    const float4* row = (const float4*)(nf + (size_t)n * IN_FEATS);
    float a0 = 0.f, a1 = 0.f;
    #pragma unroll
    for (int q = 0; q < 16; q++) {
        float4 v = row[q];
        int k = q * 4;
        a0 += v.x * Ws[(k + 0) * 2 + 0]; a1 += v.x * Ws[(k + 0) * 2 + 1];
        a0 += v.y * Ws[(k + 1) * 2 + 0]; a1 += v.y * Ws[(k + 1) * 2 + 1];
        a0 += v.z * Ws[(k + 2) * 2 + 0]; a1 += v.z * Ws[(k + 2) * 2 + 1];
        a0 += v.w * Ws[(k + 3) * 2 + 0]; a1 += v.w * Ws[(k + 3) * 2 + 1];
    }
    y2[n] = make_float2(a0, a1);
}

// vout[dst] += vin[src] + c   (float2 rows, RED.64/edge, 4 edges per thread)
// pass1: c=0 ; pass2: c=cA ; pass3: c=cB (into out, pre-seeded with b3)
__global__ void k_passv2(const float2* __restrict__ vin, float* __restrict__ vout,
                         const float* __restrict__ cvec,
                         const int* __restrict__ src, const int* __restrict__ dst) {
    int t = blockIdx.x * blockDim.x + threadIdx.x;
    if (t >= E4) return;
    float c0 = __ldg(cvec + 0), c1 = __ldg(cvec + 1);
    int4 s = ((const int4*)src)[t];
    int4 d = ((const int4*)dst)[t];
    float2 v0 = vin[s.x];
    float2 v1 = vin[s.y];
    float2 v2 = vin[s.z];
    float2 v3 = vin[s.w];
    asm volatile("red.global.add.v2.f32 [%0], {%1, %2};"
                 :: "l"(vout + (size_t)d.x * 2), "f"(v0.x + c0), "f"(v0.y + c1) : "memory");
    asm volatile("red.global.add.v2.f32 [%0], {%1, %2};"
                 :: "l"(vout + (size_t)d.y * 2), "f"(v1.x + c0), "f"(v1.y + c1) : "memory");
    asm volatile("red.global.add.v2.f32 [%0], {%1, %2};"
                 :: "l"(vout + (size_t)d.z * 2), "f"(v2.x + c0), "f"(v2.y + c1) : "memory");
    asm volatile("red.global.add.v2.f32 [%0], {%1, %2};"
                 :: "l"(vout + (size_t)d.w * 2), "f"(v3.x + c0), "f"(v3.y + c1) : "memory");
}

// ---- graph head ----
__global__ void k_gsum(const float* __restrict__ nf, const int* __restrict__ gid,
                       float* __restrict__ gsum, float* __restrict__ gcnt) {
    int t = blockIdx.x * blockDim.x + threadIdx.x;
    if (t >= CHUNKS * IN_FEATS) return;
    int f = t & (IN_FEATS - 1);
    int chunk = t >> 6;
    const int per = (N_NODES + CHUNKS - 1) / CHUNKS;
    int n0 = chunk * per;
    int n1 = n0 + per; if (n1 > N_NODES) n1 = N_NODES;
    if (n0 >= n1) return;
    float acc = 0.f;
    int curg = gid[n0];
    for (int n = n0; n < n1; n++) {
        int g = gid[n];
        if (g != curg) { atomicAdd(&gsum[curg * IN_FEATS + f], acc); acc = 0.f; curg = g; }
        acc += nf[(size_t)n * IN_FEATS + f];
    }
    atomicAdd(&gsum[curg * IN_FEATS + f], acc);
    if (f == 0) {
        float c = 0.f;
        int cg = gid[n0];
        for (int n = n0; n < n1; n++) {
            int g = gid[n];
            if (g != cg) { atomicAdd(&gcnt[cg], c); c = 0.f; cg = g; }
            c += 1.f;
        }
        atomicAdd(&gcnt[cg], c);
    }
}

__global__ void k_pred(const float* __restrict__ Wl, const float* __restrict__ bl,
                       const float* __restrict__ gsum, const float* __restrict__ gcnt,
                       float* __restrict__ out) {
    int g = threadIdx.x;
    if (g >= N_GRAPHS) return;
    float cnt = gcnt[g]; if (cnt < 1.f) cnt = 1.f;
    float s = bl[0];
    #pragma unroll 8
    for (int f = 0; f < IN_FEATS; f++)
        s += (gsum[g * IN_FEATS + f] / cnt) * Wl[f];
    out[g] = 1.f / (1.f + expf(-s));
}

extern "C" void kernel_launch(void* const* d_in, const int* in_sizes, int n_in,
                              void* d_out, int out_size) {
    const float* nf  = (const float*)d_in[0];
    // d_in[1] = edge_feats (unused by the reference model)
    const float* W1  = (const float*)d_in[2];
    const float* b1  = (const float*)d_in[3];
    const float* W2  = (const float*)d_in[4];
    const float* b2  = (const float*)d_in[5];
    const float* W3  = (const float*)d_in[6];
    const float* b3  = (const float*)d_in[7];
    const float* Wl  = (const float*)d_in[8];
    const float* bl  = (const float*)d_in[9];
    const int*   src = (const int*)d_in[10];
    const int*   dst = (const int*)d_in[11];
    const int*   gid = (const int*)d_in[12];
    float* out = (float*)d_out;

    float *p_y2, *p_z, *p_gsum, *p_gcnt, *p_W123, *p_cA, *p_cB, *p_c0;
    cudaGetSymbolAddress((void**)&p_y2,   g_y2);
    cudaGetSymbolAddress((void**)&p_z,    g_z);
    cudaGetSymbolAddress((void**)&p_gsum, g_gsum);
    cudaGetSymbolAddress((void**)&p_gcnt, g_gcnt);
    cudaGetSymbolAddress((void**)&p_W123, g_W123);
    cudaGetSymbolAddress((void**)&p_cA,   g_cA);
    cudaGetSymbolAddress((void**)&p_cB,   g_cB);
    cudaGetSymbolAddress((void**)&p_c0,   g_c0);
    float* p_z1 = p_z;
    float* p_z2 = p_z + (size_t)N_NODES * 2;

    const int T = 256;

    // fills: zero z/gsum/gcnt + seed h3 region of out with b3
    k_fills<<<(NZ4 + GS4 + GC4 + NO4 + T - 1) / T, T>>>(
        (float4*)p_z, (float4*)p_gsum, (float4*)p_gcnt,
        (float4*)(out + N_GRAPHS), b3);
    // folded weights
    k_wfold<<<1, 128>>>(W1, b1, W2, b2, W3, p_W123, p_cA, p_cB);

    // y = nf @ W123
    k_y2<<<(N_NODES + T - 1) / T, T>>>(nf, p_W123, (float2*)p_y2);

    // three 2-wide aggregation passes with bias carried through
    k_passv2<<<(E4 + T - 1) / T, T>>>((const float2*)p_y2, p_z1, p_c0, src, dst);
    k_passv2<<<(E4 + T - 1) / T, T>>>((const float2*)p_z1, p_z2, p_cA, src, dst);
    k_passv2<<<(E4 + T - 1) / T, T>>>((const float2*)p_z2, out + N_GRAPHS, p_cB, src, dst);

    // graph head: mean-pool of original features -> sigmoid(linear)
    k_gsum<<<(CHUNKS * IN_FEATS + T - 1) / T, T>>>(nf, gid, p_gsum, p_gcnt);
    k_pred<<<1, N_GRAPHS>>>(Wl, bl, p_gsum, p_gcnt, out);
}

// round 13
// speedup vs baseline: 3.3303x; 1.1920x over previous
#include <cuda_runtime.h>
#include <math.h>

#define N_NODES   100000
#define N_EDGES   1600000
#define N_GRAPHS  64
#define IN_FEATS  64
#define HIDDEN    32
#define OUT_DIM   2
#define E8        (N_EDGES / 8)
#define NWARPS    ((N_NODES + 31) / 32)    // 3125 node-chunk warps

// Scratch (device globals — no allocation allowed)
__device__ __align__(16) float g_y2 [N_NODES * 2];   // y = nf @ W123   (float2 rows)
__device__ __align__(16) float g_z  [N_NODES * 4];   // z1 = [0:2N), z2 = [2N:4N)
__device__ __align__(16) float g_gsum[N_GRAPHS * IN_FEATS];
__device__ __align__(16) float g_gcnt[N_GRAPHS];
__device__ __align__(16) float g_W123[IN_FEATS * OUT_DIM];  // W1@W2@W3  [64,2]
__device__ __align__(8) float g_cA[OUT_DIM];         // b1@W2@W3
__device__ __align__(8) float g_cB[OUT_DIM];         // b2@W3
__device__ __align__(8) float g_c0[OUT_DIM] = {0.f, 0.f};

#define NZ4  (N_NODES)                    // g_z in float4s (4N floats)
#define GS4  (N_GRAPHS * IN_FEATS / 4)
#define GC4  (N_GRAPHS / 4)
#define NO4  (N_NODES / 2)                // out h3 region in float4s (2N floats)

// One launch: zero z/gsum/gcnt AND seed out h3 region with b3 pattern
__global__ void k_fills(float4* __restrict__ z, float4* __restrict__ gsum,
                        float4* __restrict__ gcnt, float4* __restrict__ h3,
                        const float* __restrict__ b3) {
    int i = blockIdx.x * blockDim.x + threadIdx.x;
    const float4 zero = make_float4(0.f, 0.f, 0.f, 0.f);
    if (i < NZ4) { z[i] = zero; return; }
    i -= NZ4;
    if (i < GS4) { gsum[i] = zero; return; }
    i -= GS4;
    if (i < GC4) { gcnt[i] = zero; return; }
    i -= GC4;
    if (i < NO4) {
        float b0 = __ldg(b3 + 0), b1 = __ldg(b3 + 1);
        h3[i] = make_float4(b0, b1, b0, b1);
    }
}

// Fold weights: W23 = W2@W3 [32,2]; W123 = W1@W23 [64,2]; cA = b1@W23; cB = b2@W3
__global__ void k_wfold(const float* __restrict__ W1, const float* __restrict__ b1,
                        const float* __restrict__ W2, const float* __restrict__ b2,
                        const float* __restrict__ W3,
                        float* __restrict__ W123, float* __restrict__ cA,
                        float* __restrict__ cB) {
    __shared__ float W23[HIDDEN * OUT_DIM];
    int t = threadIdx.x;
    if (t < HIDDEN * OUT_DIM) {
        int i = t >> 1, j = t & 1;
        float s = 0.f;
        for (int k = 0; k < HIDDEN; k++) s += W2[i * HIDDEN + k] * W3[k * OUT_DIM + j];
        W23[t] = s;
    }
    __syncthreads();
    if (t < IN_FEATS * OUT_DIM) {
        int i = t >> 1, j = t & 1;
        float s = 0.f;
        for (int k = 0; k < HIDDEN; k++) s += W1[i * HIDDEN + k] * W23[k * OUT_DIM + j];
        W123[t] = s;
    }
    if (t < OUT_DIM) {
        float sa = 0.f, sb = 0.f;
        for (int k = 0; k < HIDDEN; k++) {
            sa += b1[k] * W23[k * OUT_DIM + t];
            sb += b2[k] * W3[k * OUT_DIM + t];
        }
        cA[t] = sa;
        cB[t] = sb;
    }
}

// Fused nf pass: warp per 32-node contiguous chunk, lane = feature pair (l, l+32).
// Produces y2 (nf@W123), gsum (per-graph feature sums), gcnt (per-graph counts).
__global__ void k_nf(const float* __restrict__ nf, const int* __restrict__ gid,
                     const float* __restrict__ W123,
                     float2* __restrict__ y2, float* __restrict__ gsum,
                     float* __restrict__ gcnt) {
    __shared__ float Ws[IN_FEATS * OUT_DIM];
    if (threadIdx.x < IN_FEATS * OUT_DIM) Ws[threadIdx.x] = W123[threadIdx.x];
    __syncthreads();
    int warp = (blockIdx.x * blockDim.x + threadIdx.x) >> 5;
    int lane = threadIdx.x & 31;
    if (warp >= NWARPS) return;
    int n0 = warp * 32;
    int n1 = n0 + 32; if (n1 > N_NODES) n1 = N_NODES;

    // weights for this lane's feature pair
    float w0a = Ws[lane * 2 + 0],        w1a = Ws[lane * 2 + 1];
    float w0b = Ws[(lane + 32) * 2 + 0], w1b = Ws[(lane + 32) * 2 + 1];

    float acc0 = 0.f, acc1 = 0.f;   // per-lane running graph sums (feat l, l+32)
    float cnt  = 0.f;
    int curg = __ldg(gid + n0);

    for (int n = n0; n < n1; n++) {
        int g = __ldg(gid + n);
        if (g != curg) {
            atomicAdd(&gsum[curg * IN_FEATS + lane],      acc0);
            atomicAdd(&gsum[curg * IN_FEATS + 32 + lane], acc1);
            if (lane == 0) atomicAdd(&gcnt[curg], cnt);
            acc0 = acc1 = cnt = 0.f;
            curg = g;
        }
        const float* row = nf + (size_t)n * IN_FEATS;
        float a = __ldg(row + lane);
        float b = __ldg(row + 32 + lane);
        acc0 += a; acc1 += b; cnt += 1.f;
        // y contribution
        float p0 = a * w0a + b * w0b;
        float p1 = a * w1a + b * w1b;
        #pragma unroll
        for (int off = 16; off > 0; off >>= 1) {
            p0 += __shfl_xor_sync(0xffffffffu, p0, off);
            p1 += __shfl_xor_sync(0xffffffffu, p1, off);
        }
        if (lane == 0) y2[n] = make_float2(p0, p1);
    }
    atomicAdd(&gsum[curg * IN_FEATS + lane],      acc0);
    atomicAdd(&gsum[curg * IN_FEATS + 32 + lane], acc1);
    if (lane == 0) atomicAdd(&gcnt[curg], cnt);
}

// vout[dst] += vin[src] + c   (float2 rows, RED.64/edge, 8 edges per thread)
// pass1: c=0 ; pass2: c=cA ; pass3: c=cB (into out, pre-seeded with b3)
__global__ void k_passv2(const float2* __restrict__ vin, float* __restrict__ vout,
                         const float* __restrict__ cvec,
                         const int* __restrict__ src, const int* __restrict__ dst) {
    int t = blockIdx.x * blockDim.x + threadIdx.x;
    if (t >= E8) return;
    float c0 = __ldg(cvec + 0), c1 = __ldg(cvec + 1);
    const int4* s4 = (const int4*)src;
    const int4* d4 = (const int4*)dst;
    int4 sa = s4[t * 2], sb = s4[t * 2 + 1];
    int4 da = d4[t * 2], db = d4[t * 2 + 1];
    float2 v0 = vin[sa.x];
    float2 v1 = vin[sa.y];
    float2 v2 = vin[sa.z];
    float2 v3 = vin[sa.w];
    float2 v4 = vin[sb.x];
    float2 v5 = vin[sb.y];
    float2 v6 = vin[sb.z];
    float2 v7 = vin[sb.w];
    asm volatile("red.global.add.v2.f32 [%0], {%1, %2};"
                 :: "l"(vout + (size_t)da.x * 2), "f"(v0.x + c0), "f"(v0.y + c1) : "memory");
    asm volatile("red.global.add.v2.f32 [%0], {%1, %2};"
                 :: "l"(vout + (size_t)da.y * 2), "f"(v1.x + c0), "f"(v1.y + c1) : "memory");
    asm volatile("red.global.add.v2.f32 [%0], {%1, %2};"
                 :: "l"(vout + (size_t)da.z * 2), "f"(v2.x + c0), "f"(v2.y + c1) : "memory");
    asm volatile("red.global.add.v2.f32 [%0], {%1, %2};"
                 :: "l"(vout + (size_t)da.w * 2), "f"(v3.x + c0), "f"(v3.y + c1) : "memory");
    asm volatile("red.global.add.v2.f32 [%0], {%1, %2};"
                 :: "l"(vout + (size_t)db.x * 2), "f"(v4.x + c0), "f"(v4.y + c1) : "memory");
    asm volatile("red.global.add.v2.f32 [%0], {%1, %2};"
                 :: "l"(vout + (size_t)db.y * 2), "f"(v5.x + c0), "f"(v5.y + c1) : "memory");
    asm volatile("red.global.add.v2.f32 [%0], {%1, %2};"
                 :: "l"(vout + (size_t)db.z * 2), "f"(v6.x + c0), "f"(v6.y + c1) : "memory");
    asm volatile("red.global.add.v2.f32 [%0], {%1, %2};"
                 :: "l"(vout + (size_t)db.w * 2), "f"(v7.x + c0), "f"(v7.y + c1) : "memory");
}

// out[g] = sigmoid( mean(nf over graph g) @ Wl + bl )
__global__ void k_pred(const float* __restrict__ Wl, const float* __restrict__ bl,
                       const float* __restrict__ gsum, const float* __restrict__ gcnt,
                       float* __restrict__ out) {
    int g = threadIdx.x;
    if (g >= N_GRAPHS) return;
    float cnt = gcnt[g]; if (cnt < 1.f) cnt = 1.f;
    float s = bl[0];
    #pragma unroll 8
    for (int f = 0; f < IN_FEATS; f++)
        s += (gsum[g * IN_FEATS + f] / cnt) * Wl[f];
    out[g] = 1.f / (1.f + expf(-s));
}

extern "C" void kernel_launch(void* const* d_in, const int* in_sizes, int n_in,
                              void* d_out, int out_size) {
    const float* nf  = (const float*)d_in[0];
    // d_in[1] = edge_feats (unused by the reference model)
    const float* W1  = (const float*)d_in[2];
    const float* b1  = (const float*)d_in[3];
    const float* W2  = (const float*)d_in[4];
    const float* b2  = (const float*)d_in[5];
    const float* W3  = (const float*)d_in[6];
    const float* b3  = (const float*)d_in[7];
    const float* Wl  = (const float*)d_in[8];
    const float* bl  = (const float*)d_in[9];
    const int*   src = (const int*)d_in[10];
    const int*   dst = (const int*)d_in[11];
    const int*   gid = (const int*)d_in[12];
    float* out = (float*)d_out;

    float *p_y2, *p_z, *p_gsum, *p_gcnt, *p_W123, *p_cA, *p_cB, *p_c0;
    cudaGetSymbolAddress((void**)&p_y2,   g_y2);
    cudaGetSymbolAddress((void**)&p_z,    g_z);
    cudaGetSymbolAddress((void**)&p_gsum, g_gsum);
    cudaGetSymbolAddress((void**)&p_gcnt, g_gcnt);
    cudaGetSymbolAddress((void**)&p_W123, g_W123);
    cudaGetSymbolAddress((void**)&p_cA,   g_cA);
    cudaGetSymbolAddress((void**)&p_cB,   g_cB);
    cudaGetSymbolAddress((void**)&p_c0,   g_c0);
    float* p_z1 = p_z;
    float* p_z2 = p_z + (size_t)N_NODES * 2;

    const int T = 256;

    // fills: zero z/gsum/gcnt + seed h3 region of out with b3
    k_fills<<<(NZ4 + GS4 + GC4 + NO4 + T - 1) / T, T>>>(
        (float4*)p_z, (float4*)p_gsum, (float4*)p_gcnt,
        (float4*)(out + N_GRAPHS), b3);
    // folded weights
    k_wfold<<<1, 128>>>(W1, b1, W2, b2, W3, p_W123, p_cA, p_cB);

    // fused nf pass: y2 + per-graph sums/counts
    k_nf<<<(NWARPS * 32 + T - 1) / T, T>>>(nf, gid, p_W123,
                                           (float2*)p_y2, p_gsum, p_gcnt);

    // three 2-wide aggregation passes with bias carried through
    k_passv2<<<(E8 + T - 1) / T, T>>>((const float2*)p_y2, p_z1, p_c0, src, dst);
    k_passv2<<<(E8 + T - 1) / T, T>>>((const float2*)p_z1, p_z2, p_cA, src, dst);
    k_passv2<<<(E8 + T - 1) / T, T>>>((const float2*)p_z2, out + N_GRAPHS, p_cB, src, dst);

    // graph head: sigmoid(mean @ Wl + bl)
    k_pred<<<1, N_GRAPHS>>>(Wl, bl, p_gsum, p_gcnt, out);
}

// round 15
// speedup vs baseline: 3.7319x; 1.1206x over previous
#include <cuda_runtime.h>
#include <math.h>

#define N_NODES   100000
#define N_EDGES   1600000
#define N_GRAPHS  64
#define IN_FEATS  64
#define HIDDEN    32
#define OUT_DIM   2
#define E4        (N_EDGES / 4)
#define NWARPS    ((N_NODES + 31) / 32)    // 3125 node-chunk warps

// Scratch (device globals — no allocation allowed)
__device__ __align__(16) float g_y2 [N_NODES * 2];   // y = nf @ W123   (float2 rows)
__device__ __align__(16) float g_z  [N_NODES * 4];   // z1 = [0:2N), z2 = [2N:4N)
__device__ __align__(16) float g_gsum[N_GRAPHS * IN_FEATS];
__device__ __align__(16) float g_gcnt[N_GRAPHS];
__device__ __align__(16) float g_W123[IN_FEATS * OUT_DIM];  // W1@W2@W3  [64,2]
__device__ __align__(8) float g_cA[OUT_DIM];         // b1@W2@W3
__device__ __align__(8) float g_cB[OUT_DIM];         // b2@W3
__device__ __align__(8) float g_c0[OUT_DIM] = {0.f, 0.f};

#define NZ4  (N_NODES)                    // g_z in float4s (4N floats)
#define GS4  (N_GRAPHS * IN_FEATS / 4)
#define GC4  (N_GRAPHS / 4)
#define NO4  (N_NODES / 2)                // out h3 region in float4s (2N floats)
#define FILL_ITEMS  (NZ4 + GS4 + GC4 + NO4)
#define FILL_BLOCKS ((FILL_ITEMS + 255) / 256)

// One launch: zero z/gsum/gcnt, seed out h3 region with b3, AND fold weights.
// The LAST block (never needed for fill work since FILL_BLOCKS covers all items
// with one spare appended) does the weight fold.
__global__ void k_init(float4* __restrict__ z, float4* __restrict__ gsum,
                       float4* __restrict__ gcnt, float4* __restrict__ h3,
                       const float* __restrict__ b3,
                       const float* __restrict__ W1, const float* __restrict__ b1,
                       const float* __restrict__ W2, const float* __restrict__ b2,
                       const float* __restrict__ W3,
                       float* __restrict__ W123, float* __restrict__ cA,
                       float* __restrict__ cB) {
    if (blockIdx.x == gridDim.x - 1) {
        // ---- weight fold (128 active threads) ----
        __shared__ float W23[HIDDEN * OUT_DIM];
        int t = threadIdx.x;
        if (t < HIDDEN * OUT_DIM) {
            int i = t >> 1, j = t & 1;
            float s = 0.f;
            for (int k = 0; k < HIDDEN; k++) s += W2[i * HIDDEN + k] * W3[k * OUT_DIM + j];
            W23[t] = s;
        }
        __syncthreads();
        if (t < IN_FEATS * OUT_DIM) {
            int i = t >> 1, j = t & 1;
            float s = 0.f;
            for (int k = 0; k < HIDDEN; k++) s += W1[i * HIDDEN + k] * W23[k * OUT_DIM + j];
            W123[t] = s;
        }
        if (t < OUT_DIM) {
            float sa = 0.f, sb = 0.f;
            for (int k = 0; k < HIDDEN; k++) {
                sa += b1[k] * W23[k * OUT_DIM + t];
                sb += b2[k] * W3[k * OUT_DIM + t];
            }
            cA[t] = sa;
            cB[t] = sb;
        }
        return;
    }
    int i = blockIdx.x * blockDim.x + threadIdx.x;
    const float4 zero = make_float4(0.f, 0.f, 0.f, 0.f);
    if (i < NZ4) { z[i] = zero; return; }
    i -= NZ4;
    if (i < GS4) { gsum[i] = zero; return; }
    i -= GS4;
    if (i < GC4) { gcnt[i] = zero; return; }
    i -= GC4;
    if (i < NO4) {
        float b0 = __ldg(b3 + 0), b1v = __ldg(b3 + 1);
        h3[i] = make_float4(b0, b1v, b0, b1v);
    }
}

// Fused nf pass: warp per 32-node contiguous chunk, lane = feature pair (l, l+32).
// Produces y2 (nf@W123), gsum (per-graph feature sums), gcnt (per-graph counts).
__global__ void k_nf(const float* __restrict__ nf, const int* __restrict__ gid,
                     const float* __restrict__ W123,
                     float2* __restrict__ y2, float* __restrict__ gsum,
                     float* __restrict__ gcnt) {
    __shared__ float Ws[IN_FEATS * OUT_DIM];
    if (threadIdx.x < IN_FEATS * OUT_DIM) Ws[threadIdx.x] = W123[threadIdx.x];
    __syncthreads();
    int warp = (blockIdx.x * blockDim.x + threadIdx.x) >> 5;
    int lane = threadIdx.x & 31;
    if (warp >= NWARPS) return;
    int n0 = warp * 32;
    int n1 = n0 + 32; if (n1 > N_NODES) n1 = N_NODES;

    float w0a = Ws[lane * 2 + 0],        w1a = Ws[lane * 2 + 1];
    float w0b = Ws[(lane + 32) * 2 + 0], w1b = Ws[(lane + 32) * 2 + 1];

    float acc0 = 0.f, acc1 = 0.f;   // per-lane running graph sums (feat l, l+32)
    float cnt  = 0.f;
    int curg = __ldg(gid + n0);

    for (int n = n0; n < n1; n++) {
        int g = __ldg(gid + n);
        if (g != curg) {
            atomicAdd(&gsum[curg * IN_FEATS + lane],      acc0);
            atomicAdd(&gsum[curg * IN_FEATS + 32 + lane], acc1);
            if (lane == 0) atomicAdd(&gcnt[curg], cnt);
            acc0 = acc1 = cnt = 0.f;
            curg = g;
        }
        const float* row = nf + (size_t)n * IN_FEATS;
        float a = __ldg(row + lane);
        float b = __ldg(row + 32 + lane);
        acc0 += a; acc1 += b; cnt += 1.f;
        float p0 = a * w0a + b * w0b;
        float p1 = a * w1a + b * w1b;
        #pragma unroll
        for (int off = 16; off > 0; off >>= 1) {
            p0 += __shfl_xor_sync(0xffffffffu, p0, off);
            p1 += __shfl_xor_sync(0xffffffffu, p1, off);
        }
        if (lane == 0) y2[n] = make_float2(p0, p1);
    }
    atomicAdd(&gsum[curg * IN_FEATS + lane],      acc0);
    atomicAdd(&gsum[curg * IN_FEATS + 32 + lane], acc1);
    if (lane == 0) atomicAdd(&gcnt[curg], cnt);
}

// vout[dst] += vin[src] + c   (float2 rows, RED.64/edge, 4 edges per thread)
// pass1: c=0 ; pass2: c=cA ; pass3: c=cB (into out, pre-seeded with b3)
__global__ void k_passv2(const float2* __restrict__ vin, float* __restrict__ vout,
                         const float* __restrict__ cvec,
                         const int* __restrict__ src, const int* __restrict__ dst) {
    int t = blockIdx.x * blockDim.x + threadIdx.x;
    if (t >= E4) return;
    float c0 = __ldg(cvec + 0), c1 = __ldg(cvec + 1);
    int4 s = ((const int4*)src)[t];
    int4 d = ((const int4*)dst)[t];
    float2 v0 = vin[s.x];
    float2 v1 = vin[s.y];
    float2 v2 = vin[s.z];
    float2 v3 = vin[s.w];
    asm volatile("red.global.add.v2.f32 [%0], {%1, %2};"
                 :: "l"(vout + (size_t)d.x * 2), "f"(v0.x + c0), "f"(v0.y + c1) : "memory");
    asm volatile("red.global.add.v2.f32 [%0], {%1, %2};"
                 :: "l"(vout + (size_t)d.y * 2), "f"(v1.x + c0), "f"(v1.y + c1) : "memory");
    asm volatile("red.global.add.v2.f32 [%0], {%1, %2};"
                 :: "l"(vout + (size_t)d.z * 2), "f"(v2.x + c0), "f"(v2.y + c1) : "memory");
    asm volatile("red.global.add.v2.f32 [%0], {%1, %2};"
                 :: "l"(vout + (size_t)d.w * 2), "f"(v3.x + c0), "f"(v3.y + c1) : "memory");
}

// out[g] = sigmoid( mean(nf over graph g) @ Wl + bl )
__global__ void k_pred(const float* __restrict__ Wl, const float* __restrict__ bl,
                       const float* __restrict__ gsum, const float* __restrict__ gcnt,
                       float* __restrict__ out) {
    int g = threadIdx.x;
    if (g >= N_GRAPHS) return;
    float cnt = gcnt[g]; if (cnt < 1.f) cnt = 1.f;
    float s = bl[0];
    #pragma unroll 8
    for (int f = 0; f < IN_FEATS; f++)
        s += (gsum[g * IN_FEATS + f] / cnt) * Wl[f];
    out[g] = 1.f / (1.f + expf(-s));
}

extern "C" void kernel_launch(void* const* d_in, const int* in_sizes, int n_in,
                              void* d_out, int out_size) {
    const float* nf  = (const float*)d_in[0];
    // d_in[1] = edge_feats (unused by the reference model)
    const float* W1  = (const float*)d_in[2];
    const float* b1  = (const float*)d_in[3];
    const float* W2  = (const float*)d_in[4];
    const float* b2  = (const float*)d_in[5];
    const float* W3  = (const float*)d_in[6];
    const float* b3  = (const float*)d_in[7];
    const float* Wl  = (const float*)d_in[8];
    const float* bl  = (const float*)d_in[9];
    const int*   src = (const int*)d_in[10];
    const int*   dst = (const int*)d_in[11];
    const int*   gid = (const int*)d_in[12];
    float* out = (float*)d_out;

    float *p_y2, *p_z, *p_gsum, *p_gcnt, *p_W123, *p_cA, *p_cB, *p_c0;
    cudaGetSymbolAddress((void**)&p_y2,   g_y2);
    cudaGetSymbolAddress((void**)&p_z,    g_z);
    cudaGetSymbolAddress((void**)&p_gsum, g_gsum);
    cudaGetSymbolAddress((void**)&p_gcnt, g_gcnt);
    cudaGetSymbolAddress((void**)&p_W123, g_W123);
    cudaGetSymbolAddress((void**)&p_cA,   g_cA);
    cudaGetSymbolAddress((void**)&p_cB,   g_cB);
    cudaGetSymbolAddress((void**)&p_c0,   g_c0);
    float* p_z1 = p_z;
    float* p_z2 = p_z + (size_t)N_NODES * 2;

    const int T = 256;

    // init: fills + b3 seed + weight fold, one launch (one spare block for the fold)
    k_init<<<FILL_BLOCKS + 1, T>>>(
        (float4*)p_z, (float4*)p_gsum, (float4*)p_gcnt,
        (float4*)(out + N_GRAPHS), b3,
        W1, b1, W2, b2, W3, p_W123, p_cA, p_cB);

    // fused nf pass: y2 + per-graph sums/counts
    k_nf<<<(NWARPS * 32 + T - 1) / T, T>>>(nf, gid, p_W123,
                                           (float2*)p_y2, p_gsum, p_gcnt);

    // graph head early (depends only on k_nf): keeps the graph tail on pass3
    k_pred<<<1, N_GRAPHS>>>(Wl, bl, p_gsum, p_gcnt, out);

    // three 2-wide aggregation passes with bias carried through (4 edges/thread)
    k_passv2<<<(E4 + T - 1) / T, T>>>((const float2*)p_y2, p_z1, p_c0, src, dst);
    k_passv2<<<(E4 + T - 1) / T, T>>>((const float2*)p_z1, p_z2, p_cA, src, dst);
    k_passv2<<<(E4 + T - 1) / T, T>>>((const float2*)p_z2, out + N_GRAPHS, p_cB, src, dst);
}